// round 12
// baseline (speedup 1.0000x reference)
#include <cuda_runtime.h>
#include <cuda_fp16.h>
#include <math.h>

#define N_NODES 10000
#define K_NBR   32
#define C_DIM   64
#define H_DIM   64
#define ALPHA   0.3f

typedef unsigned long long u64;

// Intermediates (static device arrays -> L2-resident):
// g_H[n][l] = fp16x2 of leaky(embs[n] @ Q_w + Q_b)     1.28 MB
// g_P[n][h] = embs[n] @ W_top + W_b  (fp32)            2.56 MB
__device__ __half2 g_H[N_NODES * 32];
__device__ float   g_P[N_NODES * H_DIM];

__device__ __forceinline__ u64 pack2(float x) {
    u64 r; asm("mov.b64 %0, {%1, %1};" : "=l"(r) : "f"(x)); return r;
}
__device__ __forceinline__ u64 packf2(float2 v) {
    u64 r; asm("mov.b64 %0, {%1, %2};" : "=l"(r) : "f"(v.x), "f"(v.y)); return r;
}
__device__ __forceinline__ void ffma2(u64& d, u64 a, u64 b) {
    asm("fma.rn.f32x2 %0, %1, %2, %0;" : "+l"(d) : "l"(a), "l"(b));
}
__device__ __forceinline__ float2 unpack2(u64 v) {
    float2 f; asm("mov.b64 {%0, %1}, %2;" : "=f"(f.x), "=f"(f.y) : "l"(v)); return f;
}
__device__ __forceinline__ float leaky(float x) { return x >= 0.f ? x : ALPHA * x; }

// ---------------------------------------------------------------------------
// Kernel A: per node, two 64x64 GEMVs over embs:
//   g_H = fp16(leaky(embs @ Q_w + Q_b)),  g_P = embs @ W_w[0:64] + W_b
// block = 256 (8 warps), 2 nodes/warp, grid = 625 (exact).
// ---------------------------------------------------------------------------
__global__ __launch_bounds__(256) void qproj_kernel(const float* __restrict__ embs,
                                                    const float* __restrict__ Qw,
                                                    const float* __restrict__ Qb,
                                                    const float* __restrict__ Ww,
                                                    const float* __restrict__ Wb) {
    __shared__ float2 sQ[C_DIM * 32];   // (Qw[c][2l], Qw[c][2l+1])
    __shared__ float2 sP[C_DIM * 32];   // W_top rows 0..63 of Ww
    __shared__ float  sE[8][2][C_DIM];

    const int tid  = threadIdx.x;
    const int lane = tid & 31;
    const int warp = tid >> 5;

    const float2* Q2 = (const float2*)Qw;
    const float2* W2 = (const float2*)Ww;
    for (int i = tid; i < C_DIM * 32; i += 256) { sQ[i] = Q2[i]; sP[i] = W2[i]; }
    __syncthreads();

    const int n0 = blockIdx.x * 16 + warp * 2;   // exact: 625*16 = 10000
#pragma unroll
    for (int i = 0; i < 2; ++i) {
        float2 e = ((const float2*)embs)[(n0 + i) * 32 + lane];
        *(float2*)&sE[warp][i][2 * lane] = e;
    }
    __syncwarp();

    const u64 qb = ((const u64*)Qb)[lane];
    const u64 wb = ((const u64*)Wb)[lane];
    u64 aq[2] = {qb, qb}, ap[2] = {wb, wb};

    const u64* sQ64 = (const u64*)sQ;
    const u64* sP64 = (const u64*)sP;
#pragma unroll
    for (int c = 0; c < C_DIM; c += 4) {
        u64 q0 = sQ64[(c + 0) * 32 + lane], p0 = sP64[(c + 0) * 32 + lane];
        u64 q1 = sQ64[(c + 1) * 32 + lane], p1 = sP64[(c + 1) * 32 + lane];
        u64 q2 = sQ64[(c + 2) * 32 + lane], p2 = sP64[(c + 2) * 32 + lane];
        u64 q3 = sQ64[(c + 3) * 32 + lane], p3 = sP64[(c + 3) * 32 + lane];
#pragma unroll
        for (int i = 0; i < 2; ++i) {
            float4 x = *(const float4*)&sE[warp][i][c];
            u64 x0 = pack2(x.x), x1 = pack2(x.y), x2 = pack2(x.z), x3 = pack2(x.w);
            ffma2(aq[i], x0, q0); ffma2(ap[i], x0, p0);
            ffma2(aq[i], x1, q1); ffma2(ap[i], x1, p1);
            ffma2(aq[i], x2, q2); ffma2(ap[i], x2, p2);
            ffma2(aq[i], x3, q3); ffma2(ap[i], x3, p3);
        }
    }

#pragma unroll
    for (int i = 0; i < 2; ++i) {
        float2 h = unpack2(aq[i]);
        h.x = leaky(h.x); h.y = leaky(h.y);
        g_H[(n0 + i) * 32 + lane] = __float22half2_rn(h);
        ((float2*)g_P)[(n0 + i) * 32 + lane] = unpack2(ap[i]);
    }
}

// ---------------------------------------------------------------------------
// Kernel B (fused, SINGLE-WAVE): block = 128 (4 warps), 2 nodes/warp,
// grid = 1250 (exact: 1250*8 = 10000). smem ~20.5 KB -> ~11 blocks/SM cap,
// need 8.5 -> the whole grid is resident in ONE wave: all 320K random
// weights loads are in flight within the first ~us, compute drains behind.
// Ordering inside a block: issue random loads FIRST, then 16 iters/thread of
// sV fill + g_P prefetch cover the DRAM latency before consumption.
// ---------------------------------------------------------------------------
__global__ __launch_bounds__(128) void agg_kernel(const float* __restrict__ weights,
                                                  const int*   __restrict__ nbr,
                                                  const float* __restrict__ Ww,
                                                  float* __restrict__ out) {
    __shared__ float2 sV[H_DIM * 32];   // W_bot rows 64..127 (16 KB)
    __shared__ float2 sJW[4][2][K_NBR]; // per-node (w'_k prescaled, bitcast j_k)
    __shared__ float  sX[4][2][H_DIM];  // per-warp weighted-sum-hidden vectors

    const int tid  = threadIdx.x;
    const int lane = tid & 31;
    const int warp = tid >> 5;

    const int n0 = blockIdx.x * 8 + warp * 2;   // exact, no clamp

    // ---- 1) indices + 2) issue random DRAM loads immediately ----
    int   jj[2];
    float wt[2];
#pragma unroll
    for (int i = 0; i < 2; ++i) jj[i] = nbr[(n0 + i) * K_NBR + lane];
#pragma unroll
    for (int i = 0; i < 2; ++i)
        wt[i] = __ldcs(&weights[(size_t)(n0 + i) * N_NODES + jj[i]]);  // in flight...

    // ---- 3) cover the latency: fill sV (16 KB, 16 iters/thread) + g_P ----
    const float2* W2 = (const float2*)Ww;
    for (int i = tid; i < H_DIM * 32; i += 128) sV[i] = W2[2048 + i];  // rows 64..127

    u64 o[2];
    const u64* P2 = (const u64*)g_P;
#pragma unroll
    for (int i = 0; i < 2; ++i) o[i] = P2[(n0 + i) * 32 + lane];
    __syncthreads();                               // sV ready; w loads have aged

    // ---- 4) consume random weights: reduce, prescale, stage ----
#pragma unroll
    for (int i = 0; i < 2; ++i) {
        float ws = wt[i];
#pragma unroll
        for (int off = 16; off; off >>= 1) ws += __shfl_xor_sync(0xffffffffu, ws, off);
        float inv = 1.f / (ws + 1e-6f);
        sJW[warp][i][lane] = make_float2(wt[i] * inv, __int_as_float(jj[i]));
    }
    __syncwarp();

    // ---- 5) fp16 gather + weighted accumulate (g_H L2-resident) ----
    u64 acc[2] = {0, 0};
#pragma unroll 8
    for (int k = 0; k < K_NBR; ++k) {
#pragma unroll
        for (int i = 0; i < 2; ++i) {
            float2 jw = sJW[warp][i][k];           // broadcast LDS
            int j = __float_as_int(jw.y);
            float2 hf = __half22float2(g_H[j * 32 + lane]);
            ffma2(acc[i], pack2(jw.x), packf2(hf));
        }
    }

#pragma unroll
    for (int i = 0; i < 2; ++i)
        *(float2*)&sX[warp][i][2 * lane] = unpack2(acc[i]);
    __syncwarp();

    // ---- 6) o += wsh @ W_bot ----
    const u64* sV64 = (const u64*)sV;
#pragma unroll
    for (int c = 0; c < H_DIM; c += 4) {
        u64 v0 = sV64[(c + 0) * 32 + lane];
        u64 v1 = sV64[(c + 1) * 32 + lane];
        u64 v2 = sV64[(c + 2) * 32 + lane];
        u64 v3 = sV64[(c + 3) * 32 + lane];
#pragma unroll
        for (int i = 0; i < 2; ++i) {
            float4 x = *(const float4*)&sX[warp][i][c];
            ffma2(o[i], pack2(x.x), v0);
            ffma2(o[i], pack2(x.y), v1);
            ffma2(o[i], pack2(x.z), v2);
            ffma2(o[i], pack2(x.w), v3);
        }
    }

    // ---- 7) leaky + L2-normalize + store ----
#pragma unroll
    for (int i = 0; i < 2; ++i) {
        float2 f = unpack2(o[i]);
        f.x = leaky(f.x); f.y = leaky(f.y);
        float ss = f.x * f.x + f.y * f.y;
#pragma unroll
        for (int off = 16; off; off >>= 1) ss += __shfl_xor_sync(0xffffffffu, ss, off);
        float d = 1.f / (sqrtf(ss) + 1e-6f);
        ((float2*)out)[(n0 + i) * 32 + lane] = make_float2(f.x * d, f.y * d);
    }
}

// ---------------------------------------------------------------------------
// Inputs (metadata order):
//   0 embs (1,10000,64) f32   1 weights (10000,10000) f32
//   2 neighbor_set (10000,32) i32   3 Q_w (64,64) f32   4 Q_b (64,) f32
//   5 W_w (128,64) f32   6 W_b (64,) f32
// ---------------------------------------------------------------------------
extern "C" void kernel_launch(void* const* d_in, const int* in_sizes, int n_in,
                              void* d_out, int out_size) {
    const float* embs    = (const float*)d_in[0];
    const float* weights = (const float*)d_in[1];
    const int*   nbr     = (const int*)  d_in[2];
    const float* Qw      = (const float*)d_in[3];
    const float* Qb      = (const float*)d_in[4];
    const float* Ww      = (const float*)d_in[5];
    const float* Wb      = (const float*)d_in[6];
    float* out = (float*)d_out;

    qproj_kernel<<<625, 256>>>(embs, Qw, Qb, Ww, Wb);
    agg_kernel<<<1250, 128>>>(weights, nbr, Ww, out);
}

// round 13
// speedup vs baseline: 1.0920x; 1.0920x over previous
#include <cuda_runtime.h>
#include <cuda_fp16.h>
#include <math.h>

#define N_NODES 10000
#define K_NBR   32
#define C_DIM   64
#define H_DIM   64
#define ALPHA   0.3f

typedef unsigned long long u64;

// Intermediates (static device arrays -> L2-resident):
// g_H[n][l] = fp16x2 of leaky(embs[n] @ Q_w + Q_b)     1.28 MB
// g_P[n][h] = embs[n] @ W_top + W_b  (fp32)            2.56 MB
__device__ __half2 g_H[N_NODES * 32];
__device__ float   g_P[N_NODES * H_DIM];

__device__ __forceinline__ u64 pack2(float x) {
    u64 r; asm("mov.b64 %0, {%1, %1};" : "=l"(r) : "f"(x)); return r;
}
__device__ __forceinline__ u64 packf2(float2 v) {
    u64 r; asm("mov.b64 %0, {%1, %2};" : "=l"(r) : "f"(v.x), "f"(v.y)); return r;
}
__device__ __forceinline__ void ffma2(u64& d, u64 a, u64 b) {
    asm("fma.rn.f32x2 %0, %1, %2, %0;" : "+l"(d) : "l"(a), "l"(b));
}
__device__ __forceinline__ void addf2(u64& d, u64 a) {
    asm("add.rn.f32x2 %0, %0, %1;" : "+l"(d) : "l"(a));
}
__device__ __forceinline__ float2 unpack2(u64 v) {
    float2 f; asm("mov.b64 {%0, %1}, %2;" : "=f"(f.x), "=f"(f.y) : "l"(v)); return f;
}
__device__ __forceinline__ u64 h2_to_f2(unsigned int h) {
    __half2 hv = *reinterpret_cast<__half2*>(&h);
    return packf2(__half22float2(hv));
}
__device__ __forceinline__ float leaky(float x) { return x >= 0.f ? x : ALPHA * x; }

// ---------------------------------------------------------------------------
// Kernel A: per node, two 64x64 GEMVs over embs:
//   g_H = fp16(leaky(embs @ Q_w + Q_b)),  g_P = embs @ W_w[0:64] + W_b
// block = 256 (8 warps), 2 nodes/warp, grid = 625 (exact).
// ---------------------------------------------------------------------------
__global__ __launch_bounds__(256) void qproj_kernel(const float* __restrict__ embs,
                                                    const float* __restrict__ Qw,
                                                    const float* __restrict__ Qb,
                                                    const float* __restrict__ Ww,
                                                    const float* __restrict__ Wb) {
    __shared__ float2 sQ[C_DIM * 32];   // (Qw[c][2l], Qw[c][2l+1])
    __shared__ float2 sP[C_DIM * 32];   // W_top rows 0..63 of Ww
    __shared__ float  sE[8][2][C_DIM];

    const int tid  = threadIdx.x;
    const int lane = tid & 31;
    const int warp = tid >> 5;

    const float2* Q2 = (const float2*)Qw;
    const float2* W2 = (const float2*)Ww;
    for (int i = tid; i < C_DIM * 32; i += 256) { sQ[i] = Q2[i]; sP[i] = W2[i]; }
    __syncthreads();

    const int n0 = blockIdx.x * 16 + warp * 2;   // exact: 625*16 = 10000
#pragma unroll
    for (int i = 0; i < 2; ++i) {
        float2 e = ((const float2*)embs)[(n0 + i) * 32 + lane];
        *(float2*)&sE[warp][i][2 * lane] = e;
    }
    __syncwarp();

    const u64 qb = ((const u64*)Qb)[lane];
    const u64 wb = ((const u64*)Wb)[lane];
    u64 aq[2] = {qb, qb}, ap[2] = {wb, wb};

    const u64* sQ64 = (const u64*)sQ;
    const u64* sP64 = (const u64*)sP;
#pragma unroll
    for (int c = 0; c < C_DIM; c += 4) {
        u64 q0 = sQ64[(c + 0) * 32 + lane], p0 = sP64[(c + 0) * 32 + lane];
        u64 q1 = sQ64[(c + 1) * 32 + lane], p1 = sP64[(c + 1) * 32 + lane];
        u64 q2 = sQ64[(c + 2) * 32 + lane], p2 = sP64[(c + 2) * 32 + lane];
        u64 q3 = sQ64[(c + 3) * 32 + lane], p3 = sP64[(c + 3) * 32 + lane];
#pragma unroll
        for (int i = 0; i < 2; ++i) {
            float4 x = *(const float4*)&sE[warp][i][c];
            u64 x0 = pack2(x.x), x1 = pack2(x.y), x2 = pack2(x.z), x3 = pack2(x.w);
            ffma2(aq[i], x0, q0); ffma2(ap[i], x0, p0);
            ffma2(aq[i], x1, q1); ffma2(ap[i], x1, p1);
            ffma2(aq[i], x2, q2); ffma2(ap[i], x2, p2);
            ffma2(aq[i], x3, q3); ffma2(ap[i], x3, p3);
        }
    }

#pragma unroll
    for (int i = 0; i < 2; ++i) {
        float2 h = unpack2(aq[i]);
        h.x = leaky(h.x); h.y = leaky(h.y);
        g_H[(n0 + i) * 32 + lane] = __float22half2_rn(h);
        ((float2*)g_P)[(n0 + i) * 32 + lane] = unpack2(ap[i]);
    }
}

// ---------------------------------------------------------------------------
// Kernel B (fused): random weights load first (latency covered by sV fill),
// then LDG.128 vectorized gather: warp = 4 groups x 8 lanes; iteration t,
// group g loads the full 128B fp16 row of neighbor k=4t+g (one uint4/lane),
// accumulates w'_k * row into 4 f32x2 partials, butterfly-reduced across
// groups at the end. 8 LDG.128 + 8 LDS per node (was 32+32).
// block = 256 (8 warps), 2 nodes/warp, grid = 625 (exact).
// ---------------------------------------------------------------------------
__global__ __launch_bounds__(256) void agg_kernel(const float* __restrict__ weights,
                                                  const int*   __restrict__ nbr,
                                                  const float* __restrict__ Ww,
                                                  float* __restrict__ out) {
    __shared__ float2 sV[H_DIM * 32];   // W_bot rows 64..127 (16 KB)
    __shared__ float2 sJW[8][2][K_NBR]; // per-node (w'_k prescaled, bitcast j_k)
    __shared__ float  sX[8][2][H_DIM];  // per-warp weighted-sum-hidden vectors

    const int tid  = threadIdx.x;
    const int lane = tid & 31;
    const int warp = tid >> 5;

    const int n0 = blockIdx.x * 16 + warp * 2;   // exact, no clamp

    // ---- 1) indices + 2) issue random DRAM loads immediately ----
    int   jj[2];
    float wt[2];
#pragma unroll
    for (int i = 0; i < 2; ++i) jj[i] = nbr[(n0 + i) * K_NBR + lane];
#pragma unroll
    for (int i = 0; i < 2; ++i)
        wt[i] = __ldcs(&weights[(size_t)(n0 + i) * N_NODES + jj[i]]);  // in flight...

    // ---- 3) cover the latency: fill sV (16 KB) + prefetch g_P rows ----
    const float2* W2 = (const float2*)Ww;
    for (int i = tid; i < H_DIM * 32; i += 256) sV[i] = W2[2048 + i];  // rows 64..127

    u64 o[2];
    const u64* P2 = (const u64*)g_P;
#pragma unroll
    for (int i = 0; i < 2; ++i) o[i] = P2[(n0 + i) * 32 + lane];
    __syncthreads();                               // sV ready; w loads have aged

    // ---- 4) consume random weights: reduce, prescale, stage ----
#pragma unroll
    for (int i = 0; i < 2; ++i) {
        float ws = wt[i];
#pragma unroll
        for (int off = 16; off; off >>= 1) ws += __shfl_xor_sync(0xffffffffu, ws, off);
        float inv = 1.f / (ws + 1e-6f);
        sJW[warp][i][lane] = make_float2(wt[i] * inv, __int_as_float(jj[i]));
    }
    __syncwarp();

    // ---- 5) vectorized fp16 gather (LDG.128) + weighted accumulate ----
    const int g = lane >> 3;     // group 0..3 -> neighbor k = 4t+g
    const int p = lane & 7;      // 16B chunk within the 128B row -> cols 8p..8p+7
    const uint4* H4 = (const uint4*)g_H;   // one row = 8 uint4

    u64 acc[2][4] = {{0,0,0,0},{0,0,0,0}};
#pragma unroll
    for (int t = 0; t < 8; ++t) {
#pragma unroll
        for (int i = 0; i < 2; ++i) {
            float2 jw = sJW[warp][i][4 * t + g];   // 4-way broadcast LDS
            int   j  = __float_as_int(jw.y);
            u64   wp = pack2(jw.x);
            uint4 v  = H4[j * 8 + p];              // full 128B row per group
            ffma2(acc[i][0], wp, h2_to_f2(v.x));
            ffma2(acc[i][1], wp, h2_to_f2(v.y));
            ffma2(acc[i][2], wp, h2_to_f2(v.z));
            ffma2(acc[i][3], wp, h2_to_f2(v.w));
        }
    }

    // butterfly-reduce partial column sums across the 4 groups (lanes ^8, ^16)
#pragma unroll
    for (int i = 0; i < 2; ++i) {
#pragma unroll
        for (int d = 0; d < 4; ++d) {
            addf2(acc[i][d], __shfl_xor_sync(0xffffffffu, acc[i][d], 8));
            addf2(acc[i][d], __shfl_xor_sync(0xffffffffu, acc[i][d], 16));
        }
        if (g == 0) {   // lanes 0..7 hold complete sums for cols 8p..8p+7
#pragma unroll
            for (int d = 0; d < 4; ++d)
                *(float2*)&sX[warp][i][8 * p + 2 * d] = unpack2(acc[i][d]);
        }
    }
    __syncwarp();

    // ---- 6) o += wsh @ W_bot ----
    const u64* sV64 = (const u64*)sV;
#pragma unroll
    for (int c = 0; c < H_DIM; c += 4) {
        u64 v0 = sV64[(c + 0) * 32 + lane];
        u64 v1 = sV64[(c + 1) * 32 + lane];
        u64 v2 = sV64[(c + 2) * 32 + lane];
        u64 v3 = sV64[(c + 3) * 32 + lane];
#pragma unroll
        for (int i = 0; i < 2; ++i) {
            float4 x = *(const float4*)&sX[warp][i][c];
            ffma2(o[i], pack2(x.x), v0);
            ffma2(o[i], pack2(x.y), v1);
            ffma2(o[i], pack2(x.z), v2);
            ffma2(o[i], pack2(x.w), v3);
        }
    }

    // ---- 7) leaky + L2-normalize + store ----
#pragma unroll
    for (int i = 0; i < 2; ++i) {
        float2 f = unpack2(o[i]);
        f.x = leaky(f.x); f.y = leaky(f.y);
        float ss = f.x * f.x + f.y * f.y;
#pragma unroll
        for (int off = 16; off; off >>= 1) ss += __shfl_xor_sync(0xffffffffu, ss, off);
        float d = 1.f / (sqrtf(ss) + 1e-6f);
        ((float2*)out)[(n0 + i) * 32 + lane] = make_float2(f.x * d, f.y * d);
    }
}

// ---------------------------------------------------------------------------
// Inputs (metadata order):
//   0 embs (1,10000,64) f32   1 weights (10000,10000) f32
//   2 neighbor_set (10000,32) i32   3 Q_w (64,64) f32   4 Q_b (64,) f32
//   5 W_w (128,64) f32   6 W_b (64,) f32
// ---------------------------------------------------------------------------
extern "C" void kernel_launch(void* const* d_in, const int* in_sizes, int n_in,
                              void* d_out, int out_size) {
    const float* embs    = (const float*)d_in[0];
    const float* weights = (const float*)d_in[1];
    const int*   nbr     = (const int*)  d_in[2];
    const float* Qw      = (const float*)d_in[3];
    const float* Qb      = (const float*)d_in[4];
    const float* Ww      = (const float*)d_in[5];
    const float* Wb      = (const float*)d_in[6];
    float* out = (float*)d_out;

    qproj_kernel<<<625, 256>>>(embs, Qw, Qb, Ww, Wb);
    agg_kernel<<<625, 256>>>(weights, nbr, Ww, out);
}